// round 12
// baseline (speedup 1.0000x reference)
#include <cuda_runtime.h>
#include <math.h>
#include <stdint.h>

#define QN  32
#define DN  4096
#define DIM 384
#define H2  192
#define KC    32          // K chunk (16 bf16 pairs)
#define NCH   12          // DIM / KC
#define HP    20          // hbuf row stride (u32 pairs): 16 + 4 pad, conflict-free
#define WP    200         // w2 pair-row stride (u32): 192 + 8 pad, conflict-free
#define GS    36          // gbstage row stride (floats): 32 + 4 pad
#define XP    196         // k_precompute X row stride (u32 pairs)
#define WPP   200         // k_precompute W1 tile pair-row stride (u32)

// Scratch (device globals: allocation-free per harness rules)
__device__ float    g_B[DN * DIM];          // doc_dense @ W1[384:768]
__device__ float    g_A[QN * DIM];          // query_dense @ W1[0:384] + b1
__device__ uint32_t g_W2p[(DIM / 2) * H2];  // W2 packed bf16x2 along K
__device__ uint32_t g_W1p[2 * 192 * DIM];   // W1 halves packed bf16x2

// ---------------------------------------------------------------------------
__device__ __forceinline__ uint32_t pack_bf16x2(float lo, float hi)
{
    uint32_t r;
    asm("cvt.rn.bf16x2.f32 %0, %1, %2;" : "=r"(r) : "f"(hi), "f"(lo));
    return r;
}

__device__ __forceinline__ void mma_bf16(float c[4], const uint32_t a[4],
                                         uint32_t b0, uint32_t b1)
{
    asm volatile(
        "mma.sync.aligned.m16n8k16.row.col.f32.bf16.bf16.f32 "
        "{%0,%1,%2,%3}, {%4,%5,%6,%7}, {%8,%9}, {%0,%1,%2,%3};\n"
        : "+f"(c[0]), "+f"(c[1]), "+f"(c[2]), "+f"(c[3])
        : "r"(a[0]), "r"(a[1]), "r"(a[2]), "r"(a[3]), "r"(b0), "r"(b1));
}

__device__ __forceinline__ void cp_async16(uint32_t dst_smem, const void* src)
{
    asm volatile("cp.async.cg.shared.global [%0], [%1], 16;\n"
                 :: "r"(dst_smem), "l"(src));
}
#define CP_COMMIT() asm volatile("cp.async.commit_group;\n" ::: "memory")
#define CP_WAIT0()  asm volatile("cp.async.wait_group 0;\n" ::: "memory")

__device__ __forceinline__ uint32_t smem_u32_of(const void* p)
{
    uint32_t a;
    asm("{ .reg .u64 t; cvta.to.shared.u64 t, %1; cvt.u32.u64 %0, t; }"
        : "=r"(a) : "l"(p));
    return a;
}

// ---------------------------------------------------------------------------
// Kernel 0a: pack W2 into bf16x2 pairs along K.
// ---------------------------------------------------------------------------
__global__ void __launch_bounds__(192)
k_cvtw2p(const float* __restrict__ W2)
{
    const int p = blockIdx.x;    // 0..191
    const int n = threadIdx.x;   // 0..191
    g_W2p[p * H2 + n] = pack_bf16x2(W2[(2 * p) * H2 + n],
                                    W2[(2 * p + 1) * H2 + n]);
}

// ---------------------------------------------------------------------------
// Kernel 0b: pack W1 halves into bf16x2 pairs along K.
// ---------------------------------------------------------------------------
__global__ void __launch_bounds__(384)
k_cvtw1p(const float* __restrict__ W1)
{
    const int b  = blockIdx.x;          // 0..383
    const int hs = b / 192;
    const int p  = b - hs * 192;
    const int j  = threadIdx.x;         // 0..383
    const int k0 = hs * 384 + 2 * p;
    g_W1p[hs * (192 * DIM) + p * DIM + j] =
        pack_bf16x2(W1[(size_t)k0 * DIM + j], W1[(size_t)(k0 + 1) * DIM + j]);
}

// ---------------------------------------------------------------------------
// Kernel 1: precompute A and B via bf16 mma (verified R10 version, unchanged).
// ---------------------------------------------------------------------------
__global__ void __launch_bounds__(256, 4)
k_precompute(const float* __restrict__ qd,
             const float* __restrict__ dd,
             const float* __restrict__ b1)
{
    extern __shared__ uint32_t sp_[];
    uint32_t* xs  = sp_;                 // 32*XP  = 6272 u32
    uint32_t* wst = sp_ + 32 * XP;       // 2*16*WPP = 6400 u32

    const uint32_t wst_b = smem_u32_of(sp_) + 32 * XP * 4;

    const int tid = threadIdx.x;
    const int blk = blockIdx.x;

    const float* X;
    float* outp;
    int half, hs;
    bool isQ;
    if (blk < 256) {
        const int rb = blk >> 1;
        half = blk & 1;
        hs   = 1;
        X    = dd + (size_t)rb * 32 * DIM;
        outp = g_B + (size_t)rb * 32 * DIM;
        isQ  = false;
    } else {
        half = blk - 256;
        hs   = 0;
        X    = qd;
        outp = g_A;
        isQ  = true;
    }

    const float2* X2 = (const float2*)X;
    for (int e = tid; e < 32 * 192; e += 256) {
        const int row = e / 192;
        const int p   = e - row * 192;
        const float2 v = X2[row * 192 + p];
        xs[row * XP + p] = pack_bf16x2(v.x, v.y);
    }

    const int wr = tid >> 4;
    const int wc = (tid & 15) * 12;
    const uint32_t* wsrc0 = g_W1p + (size_t)hs * (192 * DIM) + half * 192;
    const uint32_t wdst0 = wst_b + (uint32_t)(wr * WPP + wc) * 4;

    const int lane = tid & 31;
    const int w    = tid >> 5;
    const int g    = lane >> 2;
    const int tig  = lane & 3;
    const int mt   = w & 1;
    const int nh   = w >> 1;

    float acc[6][4];
#pragma unroll
    for (int nt = 0; nt < 6; nt++)
#pragma unroll
        for (int i = 0; i < 4; i++) acc[nt][i] = 0.f;

    {
        const uint32_t* src = wsrc0 + wr * DIM + wc;
#pragma unroll
        for (int i = 0; i < 3; i++) cp_async16(wdst0 + i * 16, src + i * 4);
        CP_COMMIT();
    }

    for (int c = 0; c < NCH; c++) {
        CP_WAIT0();
        __syncthreads();

        if (c < NCH - 1) {
            const int pr = (c + 1) * 16;
            const uint32_t* src = wsrc0 + (size_t)(pr + wr) * DIM + wc;
            const uint32_t wdst = wdst0 + (uint32_t)(((c + 1) & 1) * 16 * WPP) * 4;
#pragma unroll
            for (int i = 0; i < 3; i++) cp_async16(wdst + i * 16, src + i * 4);
            CP_COMMIT();
        }

        const uint32_t* w1u = wst + (c & 1) * 16 * WPP;
#pragma unroll
        for (int kp = 0; kp < 16; kp += 8) {
            uint32_t a[4];
            const int base = (mt * 16 + g) * XP + c * 16 + kp + tig;
            a[0] = xs[base];
            a[1] = xs[base + 8 * XP];
            a[2] = xs[base + 4];
            a[3] = xs[base + 8 * XP + 4];
#pragma unroll
            for (int nt = 0; nt < 6; nt++) {
                const int col = nh * 48 + nt * 8 + g;
                const uint32_t b0 = w1u[(kp + tig) * WPP + col];
                const uint32_t b1v = w1u[(kp + tig + 4) * WPP + col];
                mma_bf16(acc[nt], a, b0, b1v);
            }
        }
    }

    const int r0 = mt * 16 + g;
#pragma unroll
    for (int nt = 0; nt < 6; nt++) {
        const int ncol = nh * 48 + nt * 8 + 2 * tig;
        const int gcol = half * 192 + ncol;
        float c0 = acc[nt][0], c1 = acc[nt][1];
        float c2 = acc[nt][2], c3 = acc[nt][3];
        if (isQ) {
            const float bb0 = b1[gcol], bb1 = b1[gcol + 1];
            c0 += bb0; c1 += bb1; c2 += bb0; c3 += bb1;
        }
        *(float2*)(outp + (size_t)r0 * DIM + gcol)       = make_float2(c0, c1);
        *(float2*)(outp + (size_t)(r0 + 8) * DIM + gcol) = make_float2(c2, c3);
    }
}

// ---------------------------------------------------------------------------
// Kernel 2: dense_scores + sparse copy. Grid 512 (8 q-slices x 64 d-tiles).
// One thread per (q, d) output; unroll-8 for memory-level parallelism.
// ---------------------------------------------------------------------------
__global__ void __launch_bounds__(256)
k_dense(const float* __restrict__ qd,
        const float* __restrict__ dd,
        const float* __restrict__ sparse,
        float* __restrict__ out)
{
    __shared__ float qs[4 * DIM];    // 6 KB

    const int tid = threadIdx.x;
    const int d0  = (blockIdx.x & 63) * 64;
    const int qh  = blockIdx.x >> 6;           // 0..7
    const float* qbase = qd + qh * 4 * DIM;

    for (int e = tid; e < 4 * DIM; e += 256) qs[e] = qbase[e];
    __syncthreads();

    const int tx = tid & 63;          // doc
    const int ty = tid >> 6;          // 0..3 -> 1 q each
    const int d  = d0 + tx;
    const float* drow = dd + d * DIM;
    const float* qrow = qs + ty * DIM;

    float acc = 0.f;
#pragma unroll 8
    for (int k = 0; k < DIM; k += 4) {
        const float4 dv4 = *(const float4*)(drow + k);
        acc = fmaf(qrow[k],     dv4.x, acc);
        acc = fmaf(qrow[k + 1], dv4.y, acc);
        acc = fmaf(qrow[k + 2], dv4.z, acc);
        acc = fmaf(qrow[k + 3], dv4.w, acc);
    }

    const int q   = qh * 4 + ty;
    const int idx = q * DN + d;
    out[QN * DN + idx]     = acc;
    out[2 * QN * DN + idx] = sparse[idx];
}

// ---------------------------------------------------------------------------
// Kernel 3: main fused MLP. CTA = 2q x 64 docs (M=128), 512 threads,
// 16 warps (mp = w&3: 32-row block; nq = w>>2: 48-col quarter), ~74KB smem,
// __launch_bounds__(512,2) -> target 2 CTAs/SM. bf16 mma m16n8k16; hbuf
// double-buffered; W2 (thr 0-255) + g_B (thr 256-383) staged via cp.async.
// ---------------------------------------------------------------------------
__global__ void __launch_bounds__(512, 2)
k_main(const float* __restrict__ W1,
       const float* __restrict__ b2,
       const float* __restrict__ W3,
       const float* __restrict__ b3,
       const float* __restrict__ sparse,
       float* __restrict__ out)
{
    extern __shared__ float s3[];
    uint32_t* hbufu = (uint32_t*)s3;                  // 2 * 128*HP = 5120 u32
    uint32_t* wbufu = hbufu + 2 * 128 * HP;           // 2 * 16*WP  = 6400 u32
    float* gbst     = (float*)(wbufu + 2 * 16 * WP);  // 2 * 64*GS  = 4608 f
    float* As       = gbst + 2 * 64 * GS;             // 768 (2 q rows)
    float* wds      = As  + 768;                      // 384
    float* wsp      = wds + DIM;                      // 384
    float* b2s      = wsp + DIM;                      // 192
    float* w3s      = b2s + H2;                       // 192
    float* dss      = w3s + H2;                       // 128
    float* sps      = dss + 128;                      // 128
    float* logits   = sps + 128;                      // 128

    const uint32_t smem_b = smem_u32_of(s3);
    const uint32_t wbuf_b = smem_b + (2 * 128 * HP) * 4;
    const uint32_t gbst_b = smem_b + (2 * 128 * HP + 2 * 16 * WP) * 4;

    const int tid = threadIdx.x;
    const int blk = blockIdx.x;
    const int q0  = (blk >> 6) << 1;         // 2 q's per CTA
    const int d0  = (blk & 63) << 6;
    const float* outD = out + QN * DN;

    for (int e = tid; e < 768; e += 512)
        As[e] = g_A[(q0 + (e >= DIM)) * DIM + (e >= DIM ? e - DIM : e)];
    for (int e = tid; e < DIM; e += 512) {
        wds[e] = W1[768 * DIM + e];
        wsp[e] = W1[769 * DIM + e];
    }
    if (tid < H2) { b2s[tid] = b2[tid]; w3s[tid] = W3[tid]; }
    if (tid >= 256 && tid < 384) {
        const int t = tid - 256;
        const int idx = (q0 + (t >> 6)) * DN + d0 + (t & 63);
        dss[t] = outD[idx];
        sps[t] = sparse[idx];
        logits[t] = 0.f;
    }
    __syncthreads();

    // ---- Phase-A indexing: row r (0..127), 8-col group ----
    const int r   = tid >> 2;               // h1 row (ql*64 + dl)
    const int ql  = r >> 6;
    const int dl  = r & 63;
    const int acw = tid & 3;
    const float rds = dss[r];
    const float rsp = sps[r];

    // ---- cp.async roles ----
    const int wr = tid >> 4;                // W2: used by tid<256 (wr 0..15)
    const int wc = (tid & 15) * 12;
    const int gr = (tid - 256) >> 1;        // gbst: tid 256..383 (gr 0..63)
    const int gc = ((tid - 256) & 1) * 16;  // 16 floats = 4 cp16
    const float* gB_cp = g_B + (size_t)(d0 + (gr & 63)) * DIM + gc;

    // ---- MMA warp layout ----
    const int lane = tid & 31;
    const int w    = tid >> 5;
    const int g    = lane >> 2;
    const int tig  = lane & 3;
    const int mp   = w & 3;                 // 32-row block (0..3)
    const int nq   = w >> 2;                // 48-col quarter (0..3)

    float acc[2][6][4];
#pragma unroll
    for (int t = 0; t < 2; t++)
#pragma unroll
        for (int nt = 0; nt < 6; nt++)
#pragma unroll
            for (int i = 0; i < 4; i++) acc[t][nt][i] = 0.f;

    // ---- prologue: cp {W2(0)->wbuf0, gB(1)->gbst1}; build h0 from LDG ----
    if (tid < 256) {
        const uint32_t* srcw = g_W2p + wr * H2 + wc;
        const uint32_t wdst = wbuf_b + (uint32_t)(wr * WP + wc) * 4;
#pragma unroll
        for (int i = 0; i < 3; i++) cp_async16(wdst + i * 16, srcw + i * 4);
    } else if (tid < 384) {
        const float* srcg = gB_cp + KC;
        const uint32_t gdst = gbst_b + (uint32_t)(64 * GS + gr * GS + gc) * 4;
#pragma unroll
        for (int i = 0; i < 4; i++) cp_async16(gdst + i * 16, srcg + i * 4);
    }
    CP_COMMIT();

    {
        const float* gb = g_B + (size_t)(d0 + dl) * DIM + acw * 8;
        const float4 v0 = *(const float4*)gb;
        const float4 v1 = *(const float4*)(gb + 4);
        const int col0 = acw * 8;
        const float4 A0 = *(const float4*)(As + ql * DIM + col0);
        const float4 A1 = *(const float4*)(As + ql * DIM + col0 + 4);
        const float4 D0 = *(const float4*)(wds + col0);
        const float4 D1 = *(const float4*)(wds + col0 + 4);
        const float4 S0 = *(const float4*)(wsp + col0);
        const float4 S1 = *(const float4*)(wsp + col0 + 4);
        float x0 = fmaxf(fmaf(rsp, S0.x, fmaf(rds, D0.x, A0.x + v0.x)), 0.f);
        float x1 = fmaxf(fmaf(rsp, S0.y, fmaf(rds, D0.y, A0.y + v0.y)), 0.f);
        float x2 = fmaxf(fmaf(rsp, S0.z, fmaf(rds, D0.z, A0.z + v0.z)), 0.f);
        float x3 = fmaxf(fmaf(rsp, S0.w, fmaf(rds, D0.w, A0.w + v0.w)), 0.f);
        float x4 = fmaxf(fmaf(rsp, S1.x, fmaf(rds, D1.x, A1.x + v1.x)), 0.f);
        float x5 = fmaxf(fmaf(rsp, S1.y, fmaf(rds, D1.y, A1.y + v1.y)), 0.f);
        float x6 = fmaxf(fmaf(rsp, S1.z, fmaf(rds, D1.z, A1.z + v1.z)), 0.f);
        float x7 = fmaxf(fmaf(rsp, S1.w, fmaf(rds, D1.w, A1.w + v1.w)), 0.f);
        uint4 o = make_uint4(pack_bf16x2(x0, x1), pack_bf16x2(x2, x3),
                             pack_bf16x2(x4, x5), pack_bf16x2(x6, x7));
        *(uint4*)(hbufu + r * HP + acw * 4) = o;
    }

    for (int c = 0; c < NCH; c++) {
        CP_WAIT0();
        __syncthreads();   // prev cp visible + prev builds/MMAs done

        // issue cp for W2(c+1) and gB(c+2)
        if (c < NCH - 1) {
            if (tid < 256) {
                const int pr = (c + 1) * (KC / 2);
                const uint32_t* srcw = g_W2p + (pr + wr) * H2 + wc;
                const uint32_t wdst = wbuf_b
                    + (uint32_t)(((c + 1) & 1) * 16 * WP + wr * WP + wc) * 4;
#pragma unroll
                for (int i = 0; i < 3; i++) cp_async16(wdst + i * 16, srcw + i * 4);
            } else if (tid < 384 && c < NCH - 2) {
                const float* srcg = gB_cp + (c + 2) * KC;
                const uint32_t gdst = gbst_b
                    + (uint32_t)(((c + 2) & 1) * 64 * GS + gr * GS + gc) * 4;
#pragma unroll
                for (int i = 0; i < 4; i++) cp_async16(gdst + i * 16, srcg + i * 4);
            }
            CP_COMMIT();
        }

        // build h chunk c+1 into hbuf[(c+1)&1] from gbst[(c+1)&1]
        if (c < NCH - 1) {
            const float* gs = gbst + ((c + 1) & 1) * 64 * GS + dl * GS + acw * 8;
            const float4 v0 = ((const float4*)gs)[0];
            const float4 v1 = ((const float4*)gs)[1];
            const int col0 = (c + 1) * KC + acw * 8;
            const float4 A0 = *(const float4*)(As + ql * DIM + col0);
            const float4 A1 = *(const float4*)(As + ql * DIM + col0 + 4);
            const float4 D0 = *(const float4*)(wds + col0);
            const float4 D1 = *(const float4*)(wds + col0 + 4);
            const float4 S0 = *(const float4*)(wsp + col0);
            const float4 S1 = *(const float4*)(wsp + col0 + 4);
            float x0 = fmaxf(fmaf(rsp, S0.x, fmaf(rds, D0.x, A0.x + v0.x)), 0.f);
            float x1 = fmaxf(fmaf(rsp, S0.y, fmaf(rds, D0.y, A0.y + v0.y)), 0.f);
            float x2 = fmaxf(fmaf(rsp, S0.z, fmaf(rds, D0.z, A0.z + v0.z)), 0.f);
            float x3 = fmaxf(fmaf(rsp, S0.w, fmaf(rds, D0.w, A0.w + v0.w)), 0.f);
            float x4 = fmaxf(fmaf(rsp, S1.x, fmaf(rds, D1.x, A1.x + v1.x)), 0.f);
            float x5 = fmaxf(fmaf(rsp, S1.y, fmaf(rds, D1.y, A1.y + v1.y)), 0.f);
            float x6 = fmaxf(fmaf(rsp, S1.z, fmaf(rds, D1.z, A1.z + v1.z)), 0.f);
            float x7 = fmaxf(fmaf(rsp, S1.w, fmaf(rds, D1.w, A1.w + v1.w)), 0.f);
            uint4 o = make_uint4(pack_bf16x2(x0, x1), pack_bf16x2(x2, x3),
                                 pack_bf16x2(x4, x5), pack_bf16x2(x6, x7));
            *(uint4*)(hbufu + ((c + 1) & 1) * 128 * HP + r * HP + acw * 4) = o;
        }

        // MMA on chunk c: hbuf[c&1], wbuf[c&1]
        const uint32_t* h1u = hbufu + (c & 1) * 128 * HP;
        const uint32_t* w2u = wbufu + (c & 1) * 16 * WP;
#pragma unroll
        for (int kp = 0; kp < KC / 2; kp += 8) {
            uint32_t a[2][4];
#pragma unroll
            for (int t = 0; t < 2; t++) {
                const int base = (mp * 32 + t * 16 + g) * HP + kp + tig;
                a[t][0] = h1u[base];
                a[t][1] = h1u[base + 8 * HP];
                a[t][2] = h1u[base + 4];
                a[t][3] = h1u[base + 8 * HP + 4];
            }
#pragma unroll
            for (int nt = 0; nt < 6; nt++) {
                const int col = nq * 48 + nt * 8 + g;
                const uint32_t b0 = w2u[(kp + tig) * WP + col];
                const uint32_t b1 = w2u[(kp + tig + 4) * WP + col];
                mma_bf16(acc[0][nt], a[0], b0, b1);
                mma_bf16(acc[1][nt], a[1], b0, b1);
            }
        }
    }

    // Layer 3: relu + dot W3 on fragments
    float pr2[2][2] = {{0.f, 0.f}, {0.f, 0.f}};
#pragma unroll
    for (int t = 0; t < 2; t++)
#pragma unroll
        for (int nt = 0; nt < 6; nt++) {
            const int col = nq * 48 + nt * 8 + 2 * tig;
            float h;
            h = fmaxf(acc[t][nt][0] + b2s[col],     0.f); pr2[t][0] = fmaf(h, w3s[col],     pr2[t][0]);
            h = fmaxf(acc[t][nt][1] + b2s[col + 1], 0.f); pr2[t][0] = fmaf(h, w3s[col + 1], pr2[t][0]);
            h = fmaxf(acc[t][nt][2] + b2s[col],     0.f); pr2[t][1] = fmaf(h, w3s[col],     pr2[t][1]);
            h = fmaxf(acc[t][nt][3] + b2s[col + 1], 0.f); pr2[t][1] = fmaf(h, w3s[col + 1], pr2[t][1]);
        }

#pragma unroll
    for (int t = 0; t < 2; t++)
#pragma unroll
        for (int hseg = 0; hseg < 2; hseg++) {
            pr2[t][hseg] += __shfl_xor_sync(0xffffffffu, pr2[t][hseg], 1);
            pr2[t][hseg] += __shfl_xor_sync(0xffffffffu, pr2[t][hseg], 2);
        }

    if (tig == 0) {
#pragma unroll
        for (int t = 0; t < 2; t++) {
            atomicAdd(&logits[mp * 32 + t * 16 + g],     pr2[t][0]);
            atomicAdd(&logits[mp * 32 + t * 16 + g + 8], pr2[t][1]);
        }
    }
    __syncthreads();

    if (tid < 128) {
        const float logit = logits[tid] + b3[0];
        const float wgt   = 1.f / (1.f + expf(-logit));
        const int idx = (q0 + (tid >> 6)) * DN + d0 + (tid & 63);
        out[idx] = wgt * dss[tid] + (1.f - wgt) * sps[tid];
    }
}

// ---------------------------------------------------------------------------
extern "C" void kernel_launch(void* const* d_in, const int* in_sizes, int n_in,
                              void* d_out, int out_size)
{
    const float* qd = (const float*)d_in[0];
    const float* dd = (const float*)d_in[1];
    const float* sp = (const float*)d_in[2];
    const float* W1 = (const float*)d_in[3];
    const float* b1 = (const float*)d_in[4];
    const float* W2 = (const float*)d_in[5];
    const float* b2 = (const float*)d_in[6];
    const float* W3 = (const float*)d_in[7];
    const float* b3 = (const float*)d_in[8];
    float* out = (float*)d_out;

    const size_t smemP = (size_t)(32 * XP + 2 * 16 * WPP) * 4;       // 50,688 B
    const size_t smem3 = (size_t)(2 * 128 * HP + 2 * 16 * WP) * 4
                       + (size_t)(2 * 64 * GS + 768 + 2 * DIM + 2 * H2 + 3 * 128)
                         * 4;                                         // ~74 KB

    cudaFuncSetAttribute(k_precompute, cudaFuncAttributeMaxDynamicSharedMemorySize, (int)smemP);
    cudaFuncSetAttribute(k_main,       cudaFuncAttributeMaxDynamicSharedMemorySize, (int)smem3);

    k_cvtw2p<<<DIM / 2, 192>>>(W2);
    k_cvtw1p<<<384, 384>>>(W1);
    k_precompute<<<258, 256, smemP>>>(qd, dd, b1);
    k_dense<<<512, 256>>>(qd, dd, sp, out);
    k_main<<<(QN / 2) * (DN / 64), 512, smem3>>>(W1, b2, W3, b3, sp, out);
}

// round 15
// speedup vs baseline: 1.2060x; 1.2060x over previous
#include <cuda_runtime.h>
#include <math.h>
#include <stdint.h>

#define QN  32
#define DN  4096
#define DIM 384
#define H2  192
#define KC    32          // K chunk (16 bf16 pairs)
#define NCH   12          // DIM / KC
#define HP    20          // hbuf row stride (u32 pairs): 16 + 4 pad, conflict-free
#define WP    200         // w2 pair-row stride (u32): 192 + 8 pad, conflict-free
#define GS    36          // gbstage row stride (floats): 32 + 4 pad
#define XP    196         // k_precompute X row stride (u32 pairs)
#define WPP   200         // k_precompute W1 tile pair-row stride (u32)

// Scratch (device globals: allocation-free per harness rules)
__device__ float    g_B[DN * DIM];          // doc_dense @ W1[384:768]
__device__ float    g_A[QN * DIM];          // query_dense @ W1[0:384] + b1
__device__ uint32_t g_W2p[(DIM / 2) * H2];  // W2 packed bf16x2 along K
__device__ uint32_t g_W1p[2 * 192 * DIM];   // W1 halves packed bf16x2

// ---------------------------------------------------------------------------
__device__ __forceinline__ uint32_t pack_bf16x2(float lo, float hi)
{
    uint32_t r;
    asm("cvt.rn.bf16x2.f32 %0, %1, %2;" : "=r"(r) : "f"(hi), "f"(lo));
    return r;
}

__device__ __forceinline__ void mma_bf16(float c[4], const uint32_t a[4],
                                         uint32_t b0, uint32_t b1)
{
    asm volatile(
        "mma.sync.aligned.m16n8k16.row.col.f32.bf16.bf16.f32 "
        "{%0,%1,%2,%3}, {%4,%5,%6,%7}, {%8,%9}, {%0,%1,%2,%3};\n"
        : "+f"(c[0]), "+f"(c[1]), "+f"(c[2]), "+f"(c[3])
        : "r"(a[0]), "r"(a[1]), "r"(a[2]), "r"(a[3]), "r"(b0), "r"(b1));
}

__device__ __forceinline__ void cp_async16(uint32_t dst_smem, const void* src)
{
    asm volatile("cp.async.cg.shared.global [%0], [%1], 16;\n"
                 :: "r"(dst_smem), "l"(src));
}
#define CP_COMMIT() asm volatile("cp.async.commit_group;\n" ::: "memory")
#define CP_WAIT0()  asm volatile("cp.async.wait_group 0;\n" ::: "memory")

__device__ __forceinline__ uint32_t smem_u32_of(const void* p)
{
    uint32_t a;
    asm("{ .reg .u64 t; cvta.to.shared.u64 t, %1; cvt.u32.u64 %0, t; }"
        : "=r"(a) : "l"(p));
    return a;
}

// ---------------------------------------------------------------------------
// Kernel 0a: pack W2 into bf16x2 pairs along K.
// ---------------------------------------------------------------------------
__global__ void __launch_bounds__(192)
k_cvtw2p(const float* __restrict__ W2)
{
    const int p = blockIdx.x;    // 0..191
    const int n = threadIdx.x;   // 0..191
    g_W2p[p * H2 + n] = pack_bf16x2(W2[(2 * p) * H2 + n],
                                    W2[(2 * p + 1) * H2 + n]);
}

// ---------------------------------------------------------------------------
// Kernel 0b: pack W1 halves into bf16x2 pairs along K.
// ---------------------------------------------------------------------------
__global__ void __launch_bounds__(384)
k_cvtw1p(const float* __restrict__ W1)
{
    const int b  = blockIdx.x;          // 0..383
    const int hs = b / 192;
    const int p  = b - hs * 192;
    const int j  = threadIdx.x;         // 0..383
    const int k0 = hs * 384 + 2 * p;
    g_W1p[hs * (192 * DIM) + p * DIM + j] =
        pack_bf16x2(W1[(size_t)k0 * DIM + j], W1[(size_t)(k0 + 1) * DIM + j]);
}

// ---------------------------------------------------------------------------
// Kernel 1: precompute A and B via bf16 mma (verified R10 version, unchanged).
// ---------------------------------------------------------------------------
__global__ void __launch_bounds__(256, 4)
k_precompute(const float* __restrict__ qd,
             const float* __restrict__ dd,
             const float* __restrict__ b1)
{
    extern __shared__ uint32_t sp_[];
    uint32_t* xs  = sp_;                 // 32*XP  = 6272 u32
    uint32_t* wst = sp_ + 32 * XP;       // 2*16*WPP = 6400 u32

    const uint32_t wst_b = smem_u32_of(sp_) + 32 * XP * 4;

    const int tid = threadIdx.x;
    const int blk = blockIdx.x;

    const float* X;
    float* outp;
    int half, hs;
    bool isQ;
    if (blk < 256) {
        const int rb = blk >> 1;
        half = blk & 1;
        hs   = 1;
        X    = dd + (size_t)rb * 32 * DIM;
        outp = g_B + (size_t)rb * 32 * DIM;
        isQ  = false;
    } else {
        half = blk - 256;
        hs   = 0;
        X    = qd;
        outp = g_A;
        isQ  = true;
    }

    const float2* X2 = (const float2*)X;
    for (int e = tid; e < 32 * 192; e += 256) {
        const int row = e / 192;
        const int p   = e - row * 192;
        const float2 v = X2[row * 192 + p];
        xs[row * XP + p] = pack_bf16x2(v.x, v.y);
    }

    const int wr = tid >> 4;
    const int wc = (tid & 15) * 12;
    const uint32_t* wsrc0 = g_W1p + (size_t)hs * (192 * DIM) + half * 192;
    const uint32_t wdst0 = wst_b + (uint32_t)(wr * WPP + wc) * 4;

    const int lane = tid & 31;
    const int w    = tid >> 5;
    const int g    = lane >> 2;
    const int tig  = lane & 3;
    const int mt   = w & 1;
    const int nh   = w >> 1;

    float acc[6][4];
#pragma unroll
    for (int nt = 0; nt < 6; nt++)
#pragma unroll
        for (int i = 0; i < 4; i++) acc[nt][i] = 0.f;

    {
        const uint32_t* src = wsrc0 + wr * DIM + wc;
#pragma unroll
        for (int i = 0; i < 3; i++) cp_async16(wdst0 + i * 16, src + i * 4);
        CP_COMMIT();
    }

    for (int c = 0; c < NCH; c++) {
        CP_WAIT0();
        __syncthreads();

        if (c < NCH - 1) {
            const int pr = (c + 1) * 16;
            const uint32_t* src = wsrc0 + (size_t)(pr + wr) * DIM + wc;
            const uint32_t wdst = wdst0 + (uint32_t)(((c + 1) & 1) * 16 * WPP) * 4;
#pragma unroll
            for (int i = 0; i < 3; i++) cp_async16(wdst + i * 16, src + i * 4);
            CP_COMMIT();
        }

        const uint32_t* w1u = wst + (c & 1) * 16 * WPP;
#pragma unroll
        for (int kp = 0; kp < 16; kp += 8) {
            uint32_t a[4];
            const int base = (mt * 16 + g) * XP + c * 16 + kp + tig;
            a[0] = xs[base];
            a[1] = xs[base + 8 * XP];
            a[2] = xs[base + 4];
            a[3] = xs[base + 8 * XP + 4];
#pragma unroll
            for (int nt = 0; nt < 6; nt++) {
                const int col = nh * 48 + nt * 8 + g;
                const uint32_t b0 = w1u[(kp + tig) * WPP + col];
                const uint32_t b1v = w1u[(kp + tig + 4) * WPP + col];
                mma_bf16(acc[nt], a, b0, b1v);
            }
        }
    }

    const int r0 = mt * 16 + g;
#pragma unroll
    for (int nt = 0; nt < 6; nt++) {
        const int ncol = nh * 48 + nt * 8 + 2 * tig;
        const int gcol = half * 192 + ncol;
        float c0 = acc[nt][0], c1 = acc[nt][1];
        float c2 = acc[nt][2], c3 = acc[nt][3];
        if (isQ) {
            const float bb0 = b1[gcol], bb1 = b1[gcol + 1];
            c0 += bb0; c1 += bb1; c2 += bb0; c3 += bb1;
        }
        *(float2*)(outp + (size_t)r0 * DIM + gcol)       = make_float2(c0, c1);
        *(float2*)(outp + (size_t)(r0 + 8) * DIM + gcol) = make_float2(c2, c3);
    }
}

// ---------------------------------------------------------------------------
// Kernel 2: dense_scores + sparse copy.
// Grid 256 = 2 q-halves x 128 doc-tiles(32). 128 threads: tx=doc (0..31),
// ty=0..3 -> 4 q's each (4 independent FMA chains, R10-style ILP), 24KB smem
// -> ~8 CTAs/SM.
// ---------------------------------------------------------------------------
__global__ void __launch_bounds__(128)
k_dense(const float* __restrict__ qd,
        const float* __restrict__ dd,
        const float* __restrict__ sparse,
        float* __restrict__ out)
{
    __shared__ float qs[16 * DIM];   // 24 KB

    const int tid = threadIdx.x;
    const int d0  = (blockIdx.x & 127) * 32;
    const int qh  = blockIdx.x >> 7;           // 0 or 1
    const float* qbase = qd + qh * 16 * DIM;

    for (int e = tid; e < 16 * DIM; e += 128) qs[e] = qbase[e];
    __syncthreads();

    const int tx = tid & 31;          // doc within tile
    const int ty = tid >> 5;          // 0..3 -> 4 q's each
    const int d  = d0 + tx;
    const float* drow = dd + d * DIM;

    float acc[4];
#pragma unroll
    for (int i = 0; i < 4; i++) acc[i] = 0.f;

    for (int k = 0; k < DIM; k += 4) {
        const float4 dv4 = *(const float4*)(drow + k);
        const float dv[4] = {dv4.x, dv4.y, dv4.z, dv4.w};
#pragma unroll
        for (int t = 0; t < 4; t++)
#pragma unroll
            for (int i = 0; i < 4; i++)
                acc[i] = fmaf(qs[(ty * 4 + i) * DIM + k + t], dv[t], acc[i]);
    }

    float* outD = out + QN * DN;
    float* outS = out + 2 * QN * DN;
#pragma unroll
    for (int i = 0; i < 4; i++) {
        const int q   = qh * 16 + ty * 4 + i;
        const int idx = q * DN + d;
        outD[idx] = acc[i];
        outS[idx] = sparse[idx];
    }
}

// ---------------------------------------------------------------------------
// Kernel 3: main fused MLP (verified R9/R10 version, unchanged).
// One CTA = 1 q x 64 docs, 256 threads, ~60KB smem -> 3 CTAs/SM.
// bf16 mma m16n8k16; hbuf double-buffered; W2 + g_B staged via cp.async.
// ---------------------------------------------------------------------------
__global__ void __launch_bounds__(256, 3)
k_main(const float* __restrict__ W1,
       const float* __restrict__ b2,
       const float* __restrict__ W3,
       const float* __restrict__ b3,
       const float* __restrict__ sparse,
       float* __restrict__ out)
{
    extern __shared__ float s3[];
    uint32_t* hbufu = (uint32_t*)s3;            // 2 * 64*HP   = 2560 u32
    uint32_t* wbufu = hbufu + 2 * 64 * HP;      // 2 * 16*WP   = 6400 u32
    float* gbst     = (float*)(wbufu + 2 * 16 * WP);  // 2 * 64*GS = 4608 f
    float* As       = gbst + 2 * 64 * GS;       // 384
    float* wds      = As  + DIM;                // 384
    float* wsp      = wds + DIM;                // 384
    float* b2s      = wsp + DIM;                // 192
    float* w3s      = b2s + H2;                 // 192
    float* dss      = w3s + H2;                 // 64
    float* sps      = dss + 64;                 // 64
    float* logits   = sps + 64;                 // 64

    const uint32_t smem_u32 = smem_u32_of(s3);
    const uint32_t wbuf_b = smem_u32 + (2 * 64 * HP) * 4;
    const uint32_t gbst_b = smem_u32 + (2 * 64 * HP + 2 * 16 * WP) * 4;

    const int tid = threadIdx.x;
    const int blk = blockIdx.x;
    const int q   = blk >> 6;
    const int d0  = (blk & 63) << 6;
    const float* outD = out + QN * DN;

    for (int e = tid; e < DIM; e += 256) {
        As[e]  = g_A[q * DIM + e];
        wds[e] = W1[768 * DIM + e];
        wsp[e] = W1[769 * DIM + e];
    }
    if (tid < H2) { b2s[tid] = b2[tid]; w3s[tid] = W3[tid]; }
    if (tid < 64) {
        const int idx = q * DN + d0 + tid;
        dss[tid] = outD[idx];
        sps[tid] = sparse[idx];
        logits[tid] = 0.f;
    }
    __syncthreads();

    // ---- per-thread Phase-A indexing ----
    const int ar  = tid >> 2;               // 0..63 doc row
    const int acw = tid & 3;                // col quarter (8 cols / 4 pairs)
    const float rds = dss[ar];
    const float rsp = sps[ar];

    // ---- cp.async indexing ----
    const int wr = tid >> 4;                // 0..15 W2 pair-row
    const int wc = (tid & 15) * 12;         // 12 u32 = 48B -> 3 cp16
    const int gr = tid >> 2;                // 0..63 g_B row
    const int gc = (tid & 3) * 8;           // 8 floats = 32B -> 2 cp16
    const float* gB_base = g_B + (size_t)(d0 + gr) * DIM + gc;

    // ---- MMA warp layout ----
    const int lane = tid & 31;
    const int w    = tid >> 5;
    const int g    = lane >> 2;
    const int tig  = lane & 3;
    const int mp   = w & 1;                 // row half (32 rows)
    const int nq   = w >> 1;                // 48-col quarter

    float acc[2][6][4];
#pragma unroll
    for (int t = 0; t < 2; t++)
#pragma unroll
        for (int nt = 0; nt < 6; nt++)
#pragma unroll
            for (int i = 0; i < 4; i++) acc[t][nt][i] = 0.f;

    // ---- prologue: issue cp group {W2(0)->wbuf0, gB(1)->gbst1}, build h0 ----
    {
        const uint32_t* srcw = g_W2p + wr * H2 + wc;      // chunk 0 pairs
        const uint32_t wdst = wbuf_b + (uint32_t)(wr * WP + wc) * 4;
#pragma unroll
        for (int i = 0; i < 3; i++) cp_async16(wdst + i * 16, srcw + i * 4);
        const float* srcg = gB_base + KC;                 // chunk 1 cols
        const uint32_t gdst = gbst_b + (uint32_t)(64 * GS + gr * GS + gc) * 4;
        cp_async16(gdst,      srcg);
        cp_async16(gdst + 16, srcg + 4);
        CP_COMMIT();

        // build h chunk 0 from g_B directly (LDG)
        const float* gb = g_B + (size_t)(d0 + ar) * DIM + acw * 8;
        const float4 va = *(const float4*)gb;
        const float4 vb = *(const float4*)(gb + 4);
        const int col0 = acw * 8;
        const float4 A0 = *(const float4*)(As + col0);
        const float4 A1 = *(const float4*)(As + col0 + 4);
        const float4 D0 = *(const float4*)(wds + col0);
        const float4 D1 = *(const float4*)(wds + col0 + 4);
        const float4 S0 = *(const float4*)(wsp + col0);
        const float4 S1 = *(const float4*)(wsp + col0 + 4);
        const float v[8] = {va.x, va.y, va.z, va.w, vb.x, vb.y, vb.z, vb.w};
        const float a[8] = {A0.x, A0.y, A0.z, A0.w, A1.x, A1.y, A1.z, A1.w};
        const float dw[8] = {D0.x, D0.y, D0.z, D0.w, D1.x, D1.y, D1.z, D1.w};
        const float sw[8] = {S0.x, S0.y, S0.z, S0.w, S1.x, S1.y, S1.z, S1.w};
        float x[8];
#pragma unroll
        for (int j = 0; j < 8; j++) {
            float t0 = a[j] + v[j];
            t0 = fmaf(rds, dw[j], t0);
            t0 = fmaf(rsp, sw[j], t0);
            x[j] = fmaxf(t0, 0.f);
        }
        uint4 o = make_uint4(pack_bf16x2(x[0], x[1]), pack_bf16x2(x[2], x[3]),
                             pack_bf16x2(x[4], x[5]), pack_bf16x2(x[6], x[7]));
        *(uint4*)(hbufu + ar * HP + acw * 4) = o;
    }

    for (int c = 0; c < NCH; c++) {
        CP_WAIT0();
        __syncthreads();   // prev cp visible + all builds/MMAs of prev iter done

        // issue cp for W2(c+1) and gB(c+2)
        if (c < NCH - 1) {
            const int pr = (c + 1) * (KC / 2);   // pair base of chunk c+1
            const uint32_t* srcw = g_W2p + (pr + wr) * H2 + wc;
            const uint32_t wdst = wbuf_b
                + (uint32_t)(((c + 1) & 1) * 16 * WP + wr * WP + wc) * 4;
#pragma unroll
            for (int i = 0; i < 3; i++) cp_async16(wdst + i * 16, srcw + i * 4);
            if (c < NCH - 2) {
                const float* srcg = gB_base + (c + 2) * KC;
                const uint32_t gdst = gbst_b
                    + (uint32_t)(((c + 2) & 1) * 64 * GS + gr * GS + gc) * 4;
                cp_async16(gdst,      srcg);
                cp_async16(gdst + 16, srcg + 4);
            }
            CP_COMMIT();
        }

        // build h chunk c+1 into hbuf[(c+1)&1] from gbst[(c+1)&1]
        if (c < NCH - 1) {
            const float* gs = gbst + ((c + 1) & 1) * 64 * GS + ar * GS + acw * 8;
            const float4 va = ((const float4*)gs)[0];
            const float4 vb = ((const float4*)gs)[1];
            const int col0 = (c + 1) * KC + acw * 8;
            const float4 A0 = *(const float4*)(As + col0);
            const float4 A1 = *(const float4*)(As + col0 + 4);
            const float4 D0 = *(const float4*)(wds + col0);
            const float4 D1 = *(const float4*)(wds + col0 + 4);
            const float4 S0 = *(const float4*)(wsp + col0);
            const float4 S1 = *(const float4*)(wsp + col0 + 4);
            const float v[8] = {va.x, va.y, va.z, va.w, vb.x, vb.y, vb.z, vb.w};
            const float a[8] = {A0.x, A0.y, A0.z, A0.w, A1.x, A1.y, A1.z, A1.w};
            const float dw[8] = {D0.x, D0.y, D0.z, D0.w, D1.x, D1.y, D1.z, D1.w};
            const float sw[8] = {S0.x, S0.y, S0.z, S0.w, S1.x, S1.y, S1.z, S1.w};
            float x[8];
#pragma unroll
            for (int j = 0; j < 8; j++) {
                float t0 = a[j] + v[j];
                t0 = fmaf(rds, dw[j], t0);
                t0 = fmaf(rsp, sw[j], t0);
                x[j] = fmaxf(t0, 0.f);
            }
            uint4 o = make_uint4(pack_bf16x2(x[0], x[1]), pack_bf16x2(x[2], x[3]),
                                 pack_bf16x2(x[4], x[5]), pack_bf16x2(x[6], x[7]));
            *(uint4*)(hbufu + ((c + 1) & 1) * 64 * HP + ar * HP + acw * 4) = o;
        }

        // MMA on chunk c: hbuf[c&1], wbuf[c&1]
        const uint32_t* h1u = hbufu + (c & 1) * 64 * HP;
        const uint32_t* w2u = wbufu + (c & 1) * 16 * WP;
#pragma unroll
        for (int kp = 0; kp < KC / 2; kp += 8) {   // two k16 steps
            uint32_t a[2][4];
#pragma unroll
            for (int t = 0; t < 2; t++) {
                const int base = (mp * 32 + t * 16 + g) * HP + kp + tig;
                a[t][0] = h1u[base];
                a[t][1] = h1u[base + 8 * HP];
                a[t][2] = h1u[base + 4];
                a[t][3] = h1u[base + 8 * HP + 4];
            }
#pragma unroll
            for (int nt = 0; nt < 6; nt++) {
                const int col = nq * 48 + nt * 8 + g;
                const uint32_t b0 = w2u[(kp + tig) * WP + col];
                const uint32_t b1 = w2u[(kp + tig + 4) * WP + col];
                mma_bf16(acc[0][nt], a[0], b0, b1);
                mma_bf16(acc[1][nt], a[1], b0, b1);
            }
        }
    }

    // Layer 3: relu + dot W3 on fragments
    float pr2[2][2] = {{0.f, 0.f}, {0.f, 0.f}};
#pragma unroll
    for (int t = 0; t < 2; t++)
#pragma unroll
        for (int nt = 0; nt < 6; nt++) {
            const int col = nq * 48 + nt * 8 + 2 * tig;
            float h;
            h = fmaxf(acc[t][nt][0] + b2s[col],     0.f); pr2[t][0] = fmaf(h, w3s[col],     pr2[t][0]);
            h = fmaxf(acc[t][nt][1] + b2s[col + 1], 0.f); pr2[t][0] = fmaf(h, w3s[col + 1], pr2[t][0]);
            h = fmaxf(acc[t][nt][2] + b2s[col],     0.f); pr2[t][1] = fmaf(h, w3s[col],     pr2[t][1]);
            h = fmaxf(acc[t][nt][3] + b2s[col + 1], 0.f); pr2[t][1] = fmaf(h, w3s[col + 1], pr2[t][1]);
        }

#pragma unroll
    for (int t = 0; t < 2; t++)
#pragma unroll
        for (int hseg = 0; hseg < 2; hseg++) {
            pr2[t][hseg] += __shfl_xor_sync(0xffffffffu, pr2[t][hseg], 1);
            pr2[t][hseg] += __shfl_xor_sync(0xffffffffu, pr2[t][hseg], 2);
        }

    if (tig == 0) {
#pragma unroll
        for (int t = 0; t < 2; t++) {
            atomicAdd(&logits[mp * 32 + t * 16 + g],     pr2[t][0]);
            atomicAdd(&logits[mp * 32 + t * 16 + g + 8], pr2[t][1]);
        }
    }
    __syncthreads();

    if (tid < 64) {
        const float logit = logits[tid] + b3[0];
        const float wgt   = 1.f / (1.f + expf(-logit));
        out[q * DN + d0 + tid] = wgt * dss[tid] + (1.f - wgt) * sps[tid];
    }
}

// ---------------------------------------------------------------------------
extern "C" void kernel_launch(void* const* d_in, const int* in_sizes, int n_in,
                              void* d_out, int out_size)
{
    const float* qd = (const float*)d_in[0];
    const float* dd = (const float*)d_in[1];
    const float* sp = (const float*)d_in[2];
    const float* W1 = (const float*)d_in[3];
    const float* b1 = (const float*)d_in[4];
    const float* W2 = (const float*)d_in[5];
    const float* b2 = (const float*)d_in[6];
    const float* W3 = (const float*)d_in[7];
    const float* b3 = (const float*)d_in[8];
    float* out = (float*)d_out;

    const size_t smemP = (size_t)(32 * XP + 2 * 16 * WPP) * 4;   // 50,688 B
    const size_t smem3 = (size_t)(2 * 64 * HP + 2 * 16 * WP) * 4
                       + (size_t)(2 * 64 * GS + 3 * DIM + 2 * H2 + 3 * 64) * 4;
                       // = 61,184 B

    cudaFuncSetAttribute(k_precompute, cudaFuncAttributeMaxDynamicSharedMemorySize, (int)smemP);
    cudaFuncSetAttribute(k_main,       cudaFuncAttributeMaxDynamicSharedMemorySize, (int)smem3);

    k_cvtw2p<<<DIM / 2, 192>>>(W2);
    k_cvtw1p<<<384, 384>>>(W1);
    k_precompute<<<258, 256, smemP>>>(qd, dd, b1);
    k_dense<<<256, 128>>>(qd, dd, sp, out);
    k_main<<<(QN * DN) / 64, 256, smem3>>>(W1, b2, W3, b3, sp, out);
}

// round 17
// speedup vs baseline: 1.2526x; 1.0386x over previous
#include <cuda_runtime.h>
#include <math.h>
#include <stdint.h>

#define QN  32
#define DN  4096
#define DIM 384
#define H2  192
#define KC    32          // K chunk (16 bf16 pairs)
#define NCH   12          // DIM / KC
#define HP    20          // hbuf row stride (u32 pairs): 16 + 4 pad, conflict-free
#define WP    200         // w2 pair-row stride (u32): 192 + 8 pad, conflict-free
#define GS    36          // gbstage row stride (floats): 32 + 4 pad
#define XP    196         // k_precompute X row stride (u32 pairs)
#define WPP   200         // k_precompute W1 tile pair-row stride (u32)
#define QT    36          // k_dense qsT row stride (floats): 16B-aligned, phase-conflict-free

// Scratch (device globals: allocation-free per harness rules)
__device__ float    g_B[DN * DIM];          // doc_dense @ W1[384:768]
__device__ float    g_A[QN * DIM];          // query_dense @ W1[0:384] + b1
__device__ uint32_t g_W2p[(DIM / 2) * H2];  // W2 packed bf16x2 along K
__device__ uint32_t g_W1p[2 * 192 * DIM];   // W1 halves packed bf16x2

// ---------------------------------------------------------------------------
__device__ __forceinline__ uint32_t pack_bf16x2(float lo, float hi)
{
    uint32_t r;
    asm("cvt.rn.bf16x2.f32 %0, %1, %2;" : "=r"(r) : "f"(hi), "f"(lo));
    return r;
}

__device__ __forceinline__ void mma_bf16(float c[4], const uint32_t a[4],
                                         uint32_t b0, uint32_t b1)
{
    asm volatile(
        "mma.sync.aligned.m16n8k16.row.col.f32.bf16.bf16.f32 "
        "{%0,%1,%2,%3}, {%4,%5,%6,%7}, {%8,%9}, {%0,%1,%2,%3};\n"
        : "+f"(c[0]), "+f"(c[1]), "+f"(c[2]), "+f"(c[3])
        : "r"(a[0]), "r"(a[1]), "r"(a[2]), "r"(a[3]), "r"(b0), "r"(b1));
}

__device__ __forceinline__ void cp_async16(uint32_t dst_smem, const void* src)
{
    asm volatile("cp.async.cg.shared.global [%0], [%1], 16;\n"
                 :: "r"(dst_smem), "l"(src));
}
#define CP_COMMIT() asm volatile("cp.async.commit_group;\n" ::: "memory")
#define CP_WAIT0()  asm volatile("cp.async.wait_group 0;\n" ::: "memory")

__device__ __forceinline__ uint32_t smem_u32_of(const void* p)
{
    uint32_t a;
    asm("{ .reg .u64 t; cvta.to.shared.u64 t, %1; cvt.u32.u64 %0, t; }"
        : "=r"(a) : "l"(p));
    return a;
}

// ---------------------------------------------------------------------------
// Kernel 0a: pack W2 into bf16x2 pairs along K.
// ---------------------------------------------------------------------------
__global__ void __launch_bounds__(192)
k_cvtw2p(const float* __restrict__ W2)
{
    const int p = blockIdx.x;    // 0..191
    const int n = threadIdx.x;   // 0..191
    g_W2p[p * H2 + n] = pack_bf16x2(W2[(2 * p) * H2 + n],
                                    W2[(2 * p + 1) * H2 + n]);
}

// ---------------------------------------------------------------------------
// Kernel 0b: pack W1 halves into bf16x2 pairs along K.
// ---------------------------------------------------------------------------
__global__ void __launch_bounds__(384)
k_cvtw1p(const float* __restrict__ W1)
{
    const int b  = blockIdx.x;          // 0..383
    const int hs = b / 192;
    const int p  = b - hs * 192;
    const int j  = threadIdx.x;         // 0..383
    const int k0 = hs * 384 + 2 * p;
    g_W1p[hs * (192 * DIM) + p * DIM + j] =
        pack_bf16x2(W1[(size_t)k0 * DIM + j], W1[(size_t)(k0 + 1) * DIM + j]);
}

// ---------------------------------------------------------------------------
// Kernel 1: precompute A and B via bf16 mma (verified R10 version, unchanged).
// ---------------------------------------------------------------------------
__global__ void __launch_bounds__(256, 4)
k_precompute(const float* __restrict__ qd,
             const float* __restrict__ dd,
             const float* __restrict__ b1)
{
    extern __shared__ uint32_t sp_[];
    uint32_t* xs  = sp_;                 // 32*XP  = 6272 u32
    uint32_t* wst = sp_ + 32 * XP;       // 2*16*WPP = 6400 u32

    const uint32_t wst_b = smem_u32_of(sp_) + 32 * XP * 4;

    const int tid = threadIdx.x;
    const int blk = blockIdx.x;

    const float* X;
    float* outp;
    int half, hs;
    bool isQ;
    if (blk < 256) {
        const int rb = blk >> 1;
        half = blk & 1;
        hs   = 1;
        X    = dd + (size_t)rb * 32 * DIM;
        outp = g_B + (size_t)rb * 32 * DIM;
        isQ  = false;
    } else {
        half = blk - 256;
        hs   = 0;
        X    = qd;
        outp = g_A;
        isQ  = true;
    }

    const float2* X2 = (const float2*)X;
    for (int e = tid; e < 32 * 192; e += 256) {
        const int row = e / 192;
        const int p   = e - row * 192;
        const float2 v = X2[row * 192 + p];
        xs[row * XP + p] = pack_bf16x2(v.x, v.y);
    }

    const int wr = tid >> 4;
    const int wc = (tid & 15) * 12;
    const uint32_t* wsrc0 = g_W1p + (size_t)hs * (192 * DIM) + half * 192;
    const uint32_t wdst0 = wst_b + (uint32_t)(wr * WPP + wc) * 4;

    const int lane = tid & 31;
    const int w    = tid >> 5;
    const int g    = lane >> 2;
    const int tig  = lane & 3;
    const int mt   = w & 1;
    const int nh   = w >> 1;

    float acc[6][4];
#pragma unroll
    for (int nt = 0; nt < 6; nt++)
#pragma unroll
        for (int i = 0; i < 4; i++) acc[nt][i] = 0.f;

    {
        const uint32_t* src = wsrc0 + wr * DIM + wc;
#pragma unroll
        for (int i = 0; i < 3; i++) cp_async16(wdst0 + i * 16, src + i * 4);
        CP_COMMIT();
    }

    for (int c = 0; c < NCH; c++) {
        CP_WAIT0();
        __syncthreads();

        if (c < NCH - 1) {
            const int pr = (c + 1) * 16;
            const uint32_t* src = wsrc0 + (size_t)(pr + wr) * DIM + wc;
            const uint32_t wdst = wdst0 + (uint32_t)(((c + 1) & 1) * 16 * WPP) * 4;
#pragma unroll
            for (int i = 0; i < 3; i++) cp_async16(wdst + i * 16, src + i * 4);
            CP_COMMIT();
        }

        const uint32_t* w1u = wst + (c & 1) * 16 * WPP;
#pragma unroll
        for (int kp = 0; kp < 16; kp += 8) {
            uint32_t a[4];
            const int base = (mt * 16 + g) * XP + c * 16 + kp + tig;
            a[0] = xs[base];
            a[1] = xs[base + 8 * XP];
            a[2] = xs[base + 4];
            a[3] = xs[base + 8 * XP + 4];
#pragma unroll
            for (int nt = 0; nt < 6; nt++) {
                const int col = nh * 48 + nt * 8 + g;
                const uint32_t b0 = w1u[(kp + tig) * WPP + col];
                const uint32_t b1v = w1u[(kp + tig + 4) * WPP + col];
                mma_bf16(acc[nt], a, b0, b1v);
            }
        }
    }

    const int r0 = mt * 16 + g;
#pragma unroll
    for (int nt = 0; nt < 6; nt++) {
        const int ncol = nh * 48 + nt * 8 + 2 * tig;
        const int gcol = half * 192 + ncol;
        float c0 = acc[nt][0], c1 = acc[nt][1];
        float c2 = acc[nt][2], c3 = acc[nt][3];
        if (isQ) {
            const float bb0 = b1[gcol], bb1 = b1[gcol + 1];
            c0 += bb0; c1 += bb1; c2 += bb0; c3 += bb1;
        }
        *(float2*)(outp + (size_t)r0 * DIM + gcol)       = make_float2(c0, c1);
        *(float2*)(outp + (size_t)(r0 + 8) * DIM + gcol) = make_float2(c2, c3);
    }
}

// ---------------------------------------------------------------------------
// Kernel 2: dense_scores + sparse copy — warp-per-doc, K-interleaved lanes.
// Grid 512 x 256 thr (8 warps = 8 docs per CTA). Lane l handles k = l + 32j.
// Doc loads: LDG.32 coalesced (1 line/instr). Queries transposed in smem
// qsT[k*QT + q] (QT=36: 16B aligned, conflict-free LDS.128 phases).
// 32 fp32 accs -> butterfly register-transpose reduce -> lane l = dense[q=l].
// ---------------------------------------------------------------------------
__global__ void __launch_bounds__(256, 4)
k_dense(const float* __restrict__ qd,
        const float* __restrict__ dd,
        const float* __restrict__ sparse,
        float* __restrict__ out)
{
    extern __shared__ float qsT[];   // 384*QT = 13824 floats = 55296 B

    const int tid  = threadIdx.x;
    const int lane = tid & 31;
    const int wid  = tid >> 5;
    const int doc  = blockIdx.x * 8 + wid;

    // transpose queries: qsT[k][q] = qd[q][k]
    for (int e = tid; e < QN * DIM; e += 256) {
        const int q = e / DIM;
        const int k = e - q * DIM;
        qsT[k * QT + q] = qd[e];
    }
    __syncthreads();

    const float* drow = dd + (size_t)doc * DIM;

    // hoist the 12 coalesced doc loads (MLP=12)
    float dv[12];
#pragma unroll
    for (int j = 0; j < 12; j++) dv[j] = drow[lane + 32 * j];

    float acc[32];
#pragma unroll
    for (int q = 0; q < 32; q++) acc[q] = 0.f;

#pragma unroll
    for (int j = 0; j < 12; j++) {
        const float* qk = qsT + (lane + 32 * j) * QT;
        const float d = dv[j];
#pragma unroll
        for (int m = 0; m < 8; m++) {
            const float4 qv = *(const float4*)(qk + 4 * m);
            acc[4 * m + 0] = fmaf(qv.x, d, acc[4 * m + 0]);
            acc[4 * m + 1] = fmaf(qv.y, d, acc[4 * m + 1]);
            acc[4 * m + 2] = fmaf(qv.z, d, acc[4 * m + 2]);
            acc[4 * m + 3] = fmaf(qv.w, d, acc[4 * m + 3]);
        }
    }

    // butterfly register-transpose reduce: lane l ends with dense[q=l]
#pragma unroll
    for (int off = 16; off >= 1; off >>= 1) {
#pragma unroll
        for (int i = 0; i < 16; i++) {
            if (i < off) {
                const float a = acc[i];
                const float b = acc[i + off];
                const bool hi = (lane & off) != 0;
                const float send = hi ? a : b;
                const float keep = hi ? b : a;
                const float other = __shfl_xor_sync(0xffffffffu, send, off);
                acc[i] = keep + other;
            }
        }
    }

    // lane l: q = l. dense -> outD, sparse copy -> outS.
    const int idx = lane * DN + doc;
    out[QN * DN + idx]     = acc[0];
    out[2 * QN * DN + idx] = sparse[idx];
}

// ---------------------------------------------------------------------------
// Kernel 3: main fused MLP (verified R9/R10 version, unchanged).
// One CTA = 1 q x 64 docs, 256 threads, ~60KB smem -> 3 CTAs/SM.
// bf16 mma m16n8k16; hbuf double-buffered; W2 + g_B staged via cp.async.
// ---------------------------------------------------------------------------
__global__ void __launch_bounds__(256, 3)
k_main(const float* __restrict__ W1,
       const float* __restrict__ b2,
       const float* __restrict__ W3,
       const float* __restrict__ b3,
       const float* __restrict__ sparse,
       float* __restrict__ out)
{
    extern __shared__ float s3[];
    uint32_t* hbufu = (uint32_t*)s3;            // 2 * 64*HP   = 2560 u32
    uint32_t* wbufu = hbufu + 2 * 64 * HP;      // 2 * 16*WP   = 6400 u32
    float* gbst     = (float*)(wbufu + 2 * 16 * WP);  // 2 * 64*GS = 4608 f
    float* As       = gbst + 2 * 64 * GS;       // 384
    float* wds      = As  + DIM;                // 384
    float* wsp      = wds + DIM;                // 384
    float* b2s      = wsp + DIM;                // 192
    float* w3s      = b2s + H2;                 // 192
    float* dss      = w3s + H2;                 // 64
    float* sps      = dss + 64;                 // 64
    float* logits   = sps + 64;                 // 64

    const uint32_t smem_u32 = smem_u32_of(s3);
    const uint32_t wbuf_b = smem_u32 + (2 * 64 * HP) * 4;
    const uint32_t gbst_b = smem_u32 + (2 * 64 * HP + 2 * 16 * WP) * 4;

    const int tid = threadIdx.x;
    const int blk = blockIdx.x;
    const int q   = blk >> 6;
    const int d0  = (blk & 63) << 6;
    const float* outD = out + QN * DN;

    for (int e = tid; e < DIM; e += 256) {
        As[e]  = g_A[q * DIM + e];
        wds[e] = W1[768 * DIM + e];
        wsp[e] = W1[769 * DIM + e];
    }
    if (tid < H2) { b2s[tid] = b2[tid]; w3s[tid] = W3[tid]; }
    if (tid < 64) {
        const int idx = q * DN + d0 + tid;
        dss[tid] = outD[idx];
        sps[tid] = sparse[idx];
        logits[tid] = 0.f;
    }
    __syncthreads();

    // ---- per-thread Phase-A indexing ----
    const int ar  = tid >> 2;               // 0..63 doc row
    const int acw = tid & 3;                // col quarter (8 cols / 4 pairs)
    const float rds = dss[ar];
    const float rsp = sps[ar];

    // ---- cp.async indexing ----
    const int wr = tid >> 4;                // 0..15 W2 pair-row
    const int wc = (tid & 15) * 12;         // 12 u32 = 48B -> 3 cp16
    const int gr = tid >> 2;                // 0..63 g_B row
    const int gc = (tid & 3) * 8;           // 8 floats = 32B -> 2 cp16
    const float* gB_base = g_B + (size_t)(d0 + gr) * DIM + gc;

    // ---- MMA warp layout ----
    const int lane = tid & 31;
    const int w    = tid >> 5;
    const int g    = lane >> 2;
    const int tig  = lane & 3;
    const int mp   = w & 1;                 // row half (32 rows)
    const int nq   = w >> 1;                // 48-col quarter

    float acc[2][6][4];
#pragma unroll
    for (int t = 0; t < 2; t++)
#pragma unroll
        for (int nt = 0; nt < 6; nt++)
#pragma unroll
            for (int i = 0; i < 4; i++) acc[t][nt][i] = 0.f;

    // ---- prologue: issue cp group {W2(0)->wbuf0, gB(1)->gbst1}, build h0 ----
    {
        const uint32_t* srcw = g_W2p + wr * H2 + wc;      // chunk 0 pairs
        const uint32_t wdst = wbuf_b + (uint32_t)(wr * WP + wc) * 4;
#pragma unroll
        for (int i = 0; i < 3; i++) cp_async16(wdst + i * 16, srcw + i * 4);
        const float* srcg = gB_base + KC;                 // chunk 1 cols
        const uint32_t gdst = gbst_b + (uint32_t)(64 * GS + gr * GS + gc) * 4;
        cp_async16(gdst,      srcg);
        cp_async16(gdst + 16, srcg + 4);
        CP_COMMIT();

        // build h chunk 0 from g_B directly (LDG)
        const float* gb = g_B + (size_t)(d0 + ar) * DIM + acw * 8;
        const float4 va = *(const float4*)gb;
        const float4 vb = *(const float4*)(gb + 4);
        const int col0 = acw * 8;
        const float4 A0 = *(const float4*)(As + col0);
        const float4 A1 = *(const float4*)(As + col0 + 4);
        const float4 D0 = *(const float4*)(wds + col0);
        const float4 D1 = *(const float4*)(wds + col0 + 4);
        const float4 S0 = *(const float4*)(wsp + col0);
        const float4 S1 = *(const float4*)(wsp + col0 + 4);
        const float v[8] = {va.x, va.y, va.z, va.w, vb.x, vb.y, vb.z, vb.w};
        const float a[8] = {A0.x, A0.y, A0.z, A0.w, A1.x, A1.y, A1.z, A1.w};
        const float dw[8] = {D0.x, D0.y, D0.z, D0.w, D1.x, D1.y, D1.z, D1.w};
        const float sw[8] = {S0.x, S0.y, S0.z, S0.w, S1.x, S1.y, S1.z, S1.w};
        float x[8];
#pragma unroll
        for (int j = 0; j < 8; j++) {
            float t0 = a[j] + v[j];
            t0 = fmaf(rds, dw[j], t0);
            t0 = fmaf(rsp, sw[j], t0);
            x[j] = fmaxf(t0, 0.f);
        }
        uint4 o = make_uint4(pack_bf16x2(x[0], x[1]), pack_bf16x2(x[2], x[3]),
                             pack_bf16x2(x[4], x[5]), pack_bf16x2(x[6], x[7]));
        *(uint4*)(hbufu + ar * HP + acw * 4) = o;
    }

    for (int c = 0; c < NCH; c++) {
        CP_WAIT0();
        __syncthreads();   // prev cp visible + all builds/MMAs of prev iter done

        // issue cp for W2(c+1) and gB(c+2)
        if (c < NCH - 1) {
            const int pr = (c + 1) * (KC / 2);   // pair base of chunk c+1
            const uint32_t* srcw = g_W2p + (pr + wr) * H2 + wc;
            const uint32_t wdst = wbuf_b
                + (uint32_t)(((c + 1) & 1) * 16 * WP + wr * WP + wc) * 4;
#pragma unroll
            for (int i = 0; i < 3; i++) cp_async16(wdst + i * 16, srcw + i * 4);
            if (c < NCH - 2) {
                const float* srcg = gB_base + (c + 2) * KC;
                const uint32_t gdst = gbst_b
                    + (uint32_t)(((c + 2) & 1) * 64 * GS + gr * GS + gc) * 4;
                cp_async16(gdst,      srcg);
                cp_async16(gdst + 16, srcg + 4);
            }
            CP_COMMIT();
        }

        // build h chunk c+1 into hbuf[(c+1)&1] from gbst[(c+1)&1]
        if (c < NCH - 1) {
            const float* gs = gbst + ((c + 1) & 1) * 64 * GS + ar * GS + acw * 8;
            const float4 va = ((const float4*)gs)[0];
            const float4 vb = ((const float4*)gs)[1];
            const int col0 = (c + 1) * KC + acw * 8;
            const float4 A0 = *(const float4*)(As + col0);
            const float4 A1 = *(const float4*)(As + col0 + 4);
            const float4 D0 = *(const float4*)(wds + col0);
            const float4 D1 = *(const float4*)(wds + col0 + 4);
            const float4 S0 = *(const float4*)(wsp + col0);
            const float4 S1 = *(const float4*)(wsp + col0 + 4);
            const float v[8] = {va.x, va.y, va.z, va.w, vb.x, vb.y, vb.z, vb.w};
            const float a[8] = {A0.x, A0.y, A0.z, A0.w, A1.x, A1.y, A1.z, A1.w};
            const float dw[8] = {D0.x, D0.y, D0.z, D0.w, D1.x, D1.y, D1.z, D1.w};
            const float sw[8] = {S0.x, S0.y, S0.z, S0.w, S1.x, S1.y, S1.z, S1.w};
            float x[8];
#pragma unroll
            for (int j = 0; j < 8; j++) {
                float t0 = a[j] + v[j];
                t0 = fmaf(rds, dw[j], t0);
                t0 = fmaf(rsp, sw[j], t0);
                x[j] = fmaxf(t0, 0.f);
            }
            uint4 o = make_uint4(pack_bf16x2(x[0], x[1]), pack_bf16x2(x[2], x[3]),
                                 pack_bf16x2(x[4], x[5]), pack_bf16x2(x[6], x[7]));
            *(uint4*)(hbufu + ((c + 1) & 1) * 64 * HP + ar * HP + acw * 4) = o;
        }

        // MMA on chunk c: hbuf[c&1], wbuf[c&1]
        const uint32_t* h1u = hbufu + (c & 1) * 64 * HP;
        const uint32_t* w2u = wbufu + (c & 1) * 16 * WP;
#pragma unroll
        for (int kp = 0; kp < KC / 2; kp += 8) {   // two k16 steps
            uint32_t a[2][4];
#pragma unroll
            for (int t = 0; t < 2; t++) {
                const int base = (mp * 32 + t * 16 + g) * HP + kp + tig;
                a[t][0] = h1u[base];
                a[t][1] = h1u[base + 8 * HP];
                a[t][2] = h1u[base + 4];
                a[t][3] = h1u[base + 8 * HP + 4];
            }
#pragma unroll
            for (int nt = 0; nt < 6; nt++) {
                const int col = nq * 48 + nt * 8 + g;
                const uint32_t b0 = w2u[(kp + tig) * WP + col];
                const uint32_t b1 = w2u[(kp + tig + 4) * WP + col];
                mma_bf16(acc[0][nt], a[0], b0, b1);
                mma_bf16(acc[1][nt], a[1], b0, b1);
            }
        }
    }

    // Layer 3: relu + dot W3 on fragments
    float pr2[2][2] = {{0.f, 0.f}, {0.f, 0.f}};
#pragma unroll
    for (int t = 0; t < 2; t++)
#pragma unroll
        for (int nt = 0; nt < 6; nt++) {
            const int col = nq * 48 + nt * 8 + 2 * tig;
            float h;
            h = fmaxf(acc[t][nt][0] + b2s[col],     0.f); pr2[t][0] = fmaf(h, w3s[col],     pr2[t][0]);
            h = fmaxf(acc[t][nt][1] + b2s[col + 1], 0.f); pr2[t][0] = fmaf(h, w3s[col + 1], pr2[t][0]);
            h = fmaxf(acc[t][nt][2] + b2s[col],     0.f); pr2[t][1] = fmaf(h, w3s[col],     pr2[t][1]);
            h = fmaxf(acc[t][nt][3] + b2s[col + 1], 0.f); pr2[t][1] = fmaf(h, w3s[col + 1], pr2[t][1]);
        }

#pragma unroll
    for (int t = 0; t < 2; t++)
#pragma unroll
        for (int hseg = 0; hseg < 2; hseg++) {
            pr2[t][hseg] += __shfl_xor_sync(0xffffffffu, pr2[t][hseg], 1);
            pr2[t][hseg] += __shfl_xor_sync(0xffffffffu, pr2[t][hseg], 2);
        }

    if (tig == 0) {
#pragma unroll
        for (int t = 0; t < 2; t++) {
            atomicAdd(&logits[mp * 32 + t * 16 + g],     pr2[t][0]);
            atomicAdd(&logits[mp * 32 + t * 16 + g + 8], pr2[t][1]);
        }
    }
    __syncthreads();

    if (tid < 64) {
        const float logit = logits[tid] + b3[0];
        const float wgt   = 1.f / (1.f + expf(-logit));
        out[q * DN + d0 + tid] = wgt * dss[tid] + (1.f - wgt) * sps[tid];
    }
}

// ---------------------------------------------------------------------------
extern "C" void kernel_launch(void* const* d_in, const int* in_sizes, int n_in,
                              void* d_out, int out_size)
{
    const float* qd = (const float*)d_in[0];
    const float* dd = (const float*)d_in[1];
    const float* sp = (const float*)d_in[2];
    const float* W1 = (const float*)d_in[3];
    const float* b1 = (const float*)d_in[4];
    const float* W2 = (const float*)d_in[5];
    const float* b2 = (const float*)d_in[6];
    const float* W3 = (const float*)d_in[7];
    const float* b3 = (const float*)d_in[8];
    float* out = (float*)d_out;

    const size_t smemP = (size_t)(32 * XP + 2 * 16 * WPP) * 4;   // 50,688 B
    const size_t smemD = (size_t)(DIM * QT) * 4;                 // 55,296 B
    const size_t smem3 = (size_t)(2 * 64 * HP + 2 * 16 * WP) * 4
                       + (size_t)(2 * 64 * GS + 3 * DIM + 2 * H2 + 3 * 64) * 4;
                       // = 61,184 B

    cudaFuncSetAttribute(k_precompute, cudaFuncAttributeMaxDynamicSharedMemorySize, (int)smemP);
    cudaFuncSetAttribute(k_dense,      cudaFuncAttributeMaxDynamicSharedMemorySize, (int)smemD);
    cudaFuncSetAttribute(k_main,       cudaFuncAttributeMaxDynamicSharedMemorySize, (int)smem3);

    k_cvtw2p<<<DIM / 2, 192>>>(W2);
    k_cvtw1p<<<384, 384>>>(W1);
    k_precompute<<<258, 256, smemP>>>(qd, dd, b1);
    k_dense<<<DN / 8, 256, smemD>>>(qd, dd, sp, out);
    k_main<<<(QN * DN) / 64, 256, smem3>>>(W1, b2, W3, b3, sp, out);
}